// round 11
// baseline (speedup 1.0000x reference)
#include <cuda_runtime.h>
#include <cuda_bf16.h>
#include <math.h>

// GRUDecoder: B=8192, H=1024, V=64, T=15
#define B_MAX 8192
#define H_    1024
#define V_    64

// Device-global scratch (no runtime allocation allowed)
__device__ float g_h[B_MAX * H_];          // 32 MB  hidden state (exact fp32)
__device__ float g_gh[B_MAX * 3 * H_];     // 96 MB  gh = fp32 gemm(h,Whh) + bhh
__device__ float g_GI[V_ * 3 * H_];        // GI[v][c] = W_ih[c,v] + b_ih[c]
__device__ int   g_tok[B_MAX];             // greedy feedback tokens

// XLA's f32 tanh (elemental_ir_emitter / Eigen generic_fast_tanh_float).
// fmaf + IEEE div => immune to --use_fast_math.
__device__ __forceinline__ float tanh_xla(float x) {
    const float kClamp = 7.90531110763549805f;
    float xc = fminf(fmaxf(x, -kClamp), kClamp);
    float x2 = __fmul_rn(xc, xc);
    float p = -2.76076847742355e-16f;
    p = fmaf(p, x2, 2.00018790482477e-13f);
    p = fmaf(p, x2, -8.60467152213735e-11f);
    p = fmaf(p, x2, 5.12229709037114e-08f);
    p = fmaf(p, x2, 1.48572235717979e-05f);
    p = fmaf(p, x2, 6.37261928875436e-04f);
    p = fmaf(p, x2, 4.89352455891786e-03f);
    p = __fmul_rn(p, xc);
    float q = 1.19825839466702e-06f;
    q = fmaf(q, x2, 1.18534705686654e-04f);
    q = fmaf(q, x2, 2.26843463243900e-03f);
    q = fmaf(q, x2, 4.89352518554385e-03f);
    float r = __fdiv_rn(p, q);
    return (fabsf(x) < 0.0004f) ? x : r;
}

// XLA logistic lowering: 0.5 + 0.5 * tanh(0.5 * x)  (pinned rounding)
__device__ __forceinline__ float sigmoid_xla(float x) {
    float t = tanh_xla(__fmul_rn(0.5f, x));
    return __fadd_rn(0.5f, __fmul_rn(0.5f, t));
}

// ---------------------------------------------------------------------------
// GI[v][c] = W_ih[c,v] + b_ih[c]  (exact fp32; one-hot dot is exact in any
// precision: 63 zero terms + 1.0 * W).
// ---------------------------------------------------------------------------
__global__ void build_gi_kernel(const float* __restrict__ Wih,
                                const float* __restrict__ bih)
{
    int idx = blockIdx.x * blockDim.x + threadIdx.x;
    if (idx >= V_ * 3 * H_) return;
    int v = idx / (3 * H_);
    int c = idx % (3 * H_);
    g_GI[idx] = __fadd_rn(Wih[(size_t)c * V_ + v], bih[c]);
}

// ---------------------------------------------------------------------------
// gh = h @ W_hh^T + b_hh, plain exact fp32 FMA.  M=8192, N=3072, K=1024.
// ---------------------------------------------------------------------------
#define BM 128
#define BN 128
#define BK 16

__global__ __launch_bounds__(256, 2)
void gru_gemm_kernel(const float* __restrict__ ctx,
                     const float* __restrict__ Whh,
                     const float* __restrict__ bhh,
                     int use_ctx)
{
    const float* __restrict__ A = use_ctx ? ctx : g_h;
    float* __restrict__ C = g_gh;
    const int K = H_;
    const int N = 3 * H_;

    const int m0 = blockIdx.y * BM;
    const int n0 = blockIdx.x * BN;

    __shared__ float As[BK][BM + 4];
    __shared__ float Bs[BK][BN + 4];

    const int tid = threadIdx.x;
    const int tx = tid & 15;   // n micro
    const int ty = tid >> 4;   // m micro

    const int lrow = tid >> 2;        // 0..63
    const int lc4  = (tid & 3) << 2;  // 0,4,8,12

    float acc[8][8];
#pragma unroll
    for (int i = 0; i < 8; ++i)
#pragma unroll
        for (int j = 0; j < 8; ++j) acc[i][j] = 0.0f;

    for (int kt = 0; kt < K; kt += BK) {
#pragma unroll
        for (int r = 0; r < 2; ++r) {
            int m = lrow + r * 64;
            float4 a = *(const float4*)(A   + (size_t)(m0 + m) * K + kt + lc4);
            As[lc4 + 0][m] = a.x; As[lc4 + 1][m] = a.y;
            As[lc4 + 2][m] = a.z; As[lc4 + 3][m] = a.w;
            float4 b = *(const float4*)(Whh + (size_t)(n0 + m) * K + kt + lc4);
            Bs[lc4 + 0][m] = b.x; Bs[lc4 + 1][m] = b.y;
            Bs[lc4 + 2][m] = b.z; Bs[lc4 + 3][m] = b.w;
        }
        __syncthreads();

#pragma unroll
        for (int k = 0; k < BK; ++k) {
            float ra[8], rb[8];
#pragma unroll
            for (int i = 0; i < 8; ++i) ra[i] = As[k][ty * 8 + i];
#pragma unroll
            for (int j = 0; j < 8; ++j) rb[j] = Bs[k][tx * 8 + j];
#pragma unroll
            for (int i = 0; i < 8; ++i)
#pragma unroll
                for (int j = 0; j < 8; ++j)
                    acc[i][j] = fmaf(ra[i], rb[j], acc[i][j]);
        }
        __syncthreads();
    }

#pragma unroll
    for (int i = 0; i < 8; ++i) {
        int m = m0 + ty * 8 + i;
#pragma unroll
        for (int j = 0; j < 8; j += 4) {
            int n = n0 + tx * 8 + j;
            float4 o;
            o.x = __fadd_rn(acc[i][j + 0], bhh[n + 0]);
            o.y = __fadd_rn(acc[i][j + 1], bhh[n + 1]);
            o.z = __fadd_rn(acc[i][j + 2], bhh[n + 2]);
            o.w = __fadd_rn(acc[i][j + 3], bhh[n + 3]);
            *(float4*)(C + (size_t)m * N + n) = o;
        }
    }
}

// ---------------------------------------------------------------------------
// Per-batch-row fused update, numerics pinned to the jnp lowering:
//   r = logistic(i_r + h_r); z = logistic(i_z + h_z)
//   n = tanh(i_n + r*h_n)                        (mul then add, no fma)
//   h = (1-z)*n + z*h                            (two muls, one add)
//   logits fp32 dot; logp = (x - m) - log(sum(exp(x - m)))
//   pred = argmax over the FINAL rounded logp values (first-index ties).
// ---------------------------------------------------------------------------
__global__ __launch_bounds__(256)
void gru_update_kernel(const float* __restrict__ ctx,
                       const float* __restrict__ Wout,
                       const float* __restrict__ bout,
                       float* __restrict__ logp_out,   // [B, T, V]
                       float* __restrict__ pred_out,   // [B, T] as float, or null
                       int t, int T, int use_ctx)
{
    const int b   = blockIdx.x;
    const int tid = threadIdx.x;

    const int tk = use_ctx ? 0 : g_tok[b];
    const float* __restrict__ gi  = g_GI + (size_t)tk * 3 * H_;
    const float* __restrict__ ghb = g_gh + (size_t)b  * 3 * H_;
    const float* __restrict__ hin = (use_ctx ? ctx : g_h) + (size_t)b * H_;

    __shared__ float sh[H_];   // exact fp32 h (logits input)

    for (int j = tid; j < H_; j += 256) {
        float r = sigmoid_xla(__fadd_rn(gi[j],          ghb[j]));
        float z = sigmoid_xla(__fadd_rn(gi[j + H_],     ghb[j + H_]));
        float rn = __fmul_rn(r, ghb[j + 2 * H_]);
        float n  = tanh_xla(__fadd_rn(gi[j + 2 * H_], rn));
        float a1 = __fmul_rn(__fsub_rn(1.0f, z), n);
        float a2 = __fmul_rn(z, hin[j]);
        float hv = __fadd_rn(a1, a2);
        sh[j] = hv;
        g_h[(size_t)b * H_ + j] = hv;
    }
    __syncthreads();

    // logits: warp w handles vocab rows v = w*8 .. w*8+7, fp32 dot over H
    const int warp = tid >> 5;
    const int lane = tid & 31;
    __shared__ float slog[V_];

    const float4* __restrict__ h4 = (const float4*)sh;
#pragma unroll
    for (int vi = 0; vi < 8; ++vi) {
        int v = warp * 8 + vi;
        const float4* __restrict__ w4 = (const float4*)(Wout + (size_t)v * H_);
        float acc = 0.0f;
#pragma unroll
        for (int i = 0; i < H_ / 128; ++i) {   // 8 iterations of float4
            float4 a  = w4[lane + i * 32];
            float4 hh = h4[lane + i * 32];
            acc = fmaf(a.x, hh.x, acc);
            acc = fmaf(a.y, hh.y, acc);
            acc = fmaf(a.z, hh.z, acc);
            acc = fmaf(a.w, hh.w, acc);
        }
#pragma unroll
        for (int off = 16; off > 0; off >>= 1)
            acc += __shfl_down_sync(0xffffffffu, acc, off);
        if (lane == 0) slog[v] = __fadd_rn(acc, bout[v]);
    }
    __syncthreads();

    // log-softmax + argmax, single thread per row (V=64, cheap), numerics
    // pinned: shifted = x - m (fp32); lse = log(sum(exp(shifted))) (double,
    // deterministic); logp = shifted - lse (fp32); argmax over rounded logp.
    __shared__ float s_shift[V_];
    __shared__ float s_lsef;
    if (tid == 0) {
        float mx = slog[0];
        for (int v = 1; v < V_; ++v) mx = fmaxf(mx, slog[v]);
        double s = 0.0;
        for (int v = 0; v < V_; ++v) {
            float sv = __fsub_rn(slog[v], mx);
            s_shift[v] = sv;
            s += exp((double)sv);
        }
        s_lsef = (float)log(s);
    }
    __syncthreads();

    if (tid < V_) {
        logp_out[((size_t)b * T + t) * V_ + tid] =
            __fsub_rn(s_shift[tid], s_lsef);
    }

    if (tid == 0) {
        float lse = s_lsef;
        float best = __fsub_rn(s_shift[0], lse);
        int am = 0;
        for (int v = 1; v < V_; ++v) {
            float lp = __fsub_rn(s_shift[v], lse);
            if (lp > best) { best = lp; am = v; }   // first-index tie break
        }
        g_tok[b] = am;
        if (pred_out) pred_out[(size_t)b * T + t] = (float)am;
    }
}

// ---------------------------------------------------------------------------
// Launch
// ---------------------------------------------------------------------------
extern "C" void kernel_launch(void* const* d_in, const int* in_sizes, int n_in,
                              void* d_out, int out_size)
{
    const float* ctx  = (const float*)d_in[0];  // [B, H]
    const float* Wih  = (const float*)d_in[1];  // [3H, V]
    const float* Whh  = (const float*)d_in[2];  // [3H, H]
    const float* bih  = (const float*)d_in[3];  // [3H]
    const float* bhh  = (const float*)d_in[4];  // [3H]
    const float* Wout = (const float*)d_in[5];  // [V, H]
    const float* bout = (const float*)d_in[6];  // [V]

    const int B = in_sizes[0] / H_;

    // Output layout: logps [B,T,V] possibly followed by preds [B,T] (float).
    float* out = (float*)d_out;
    float* logp_out = out;
    float* pred_out = nullptr;
    int T;
    const long per_both = (long)B * (V_ + 1);
    const long per_logp = (long)B * V_;
    if ((long)out_size % per_both == 0) {
        T = (int)((long)out_size / per_both);
        pred_out = out + (size_t)B * T * V_;
    } else {
        T = (int)((long)out_size / per_logp);
    }

    // Build GI table (exact fp32 W_ih column + bias)
    {
        int total = V_ * 3 * H_;
        build_gi_kernel<<<(total + 255) / 256, 256>>>(Wih, bih);
    }

    dim3 gemm_grid(3 * H_ / BN, B / BM);
    for (int t = 0; t < T; ++t) {
        int use_ctx = (t == 0) ? 1 : 0;
        gru_gemm_kernel<<<gemm_grid, 256>>>(ctx, Whh, bhh, use_ctx);
        gru_update_kernel<<<B, 256>>>(ctx, Wout, bout, logp_out, pred_out,
                                      t, T, use_ctx);
    }
}

// round 12
// speedup vs baseline: 1.1118x; 1.1118x over previous
#include <cuda_runtime.h>
#include <cuda_bf16.h>
#include <math.h>

// GRUDecoder: B=8192, H=1024, V=64, T=15
#define B_MAX 8192
#define H_    1024
#define V_    64
#define ROWS  8     // batch rows per update block

// Device-global scratch (no runtime allocation allowed)
__device__ float g_h[B_MAX * H_];          // 32 MB  hidden state (exact fp32)
__device__ float g_gh[B_MAX * 3 * H_];     // 96 MB  gh = fp32 gemm(h,Whh) + bhh
__device__ float g_GI[V_ * 3 * H_];        // GI[v][c] = W_ih[c,v] + b_ih[c]
__device__ int   g_tok[B_MAX];             // greedy feedback tokens

// XLA's f32 tanh (elemental_ir_emitter / Eigen generic_fast_tanh_float).
// fmaf + IEEE div => immune to --use_fast_math.
__device__ __forceinline__ float tanh_xla(float x) {
    const float kClamp = 7.90531110763549805f;
    float xc = fminf(fmaxf(x, -kClamp), kClamp);
    float x2 = __fmul_rn(xc, xc);
    float p = -2.76076847742355e-16f;
    p = fmaf(p, x2, 2.00018790482477e-13f);
    p = fmaf(p, x2, -8.60467152213735e-11f);
    p = fmaf(p, x2, 5.12229709037114e-08f);
    p = fmaf(p, x2, 1.48572235717979e-05f);
    p = fmaf(p, x2, 6.37261928875436e-04f);
    p = fmaf(p, x2, 4.89352455891786e-03f);
    p = __fmul_rn(p, xc);
    float q = 1.19825839466702e-06f;
    q = fmaf(q, x2, 1.18534705686654e-04f);
    q = fmaf(q, x2, 2.26843463243900e-03f);
    q = fmaf(q, x2, 4.89352518554385e-03f);
    float r = __fdiv_rn(p, q);
    return (fabsf(x) < 0.0004f) ? x : r;
}

// XLA logistic lowering: 0.5 + 0.5 * tanh(0.5 * x)  (pinned rounding)
__device__ __forceinline__ float sigmoid_xla(float x) {
    float t = tanh_xla(__fmul_rn(0.5f, x));
    return __fadd_rn(0.5f, __fmul_rn(0.5f, t));
}

// ---------------------------------------------------------------------------
// GI[v][c] = W_ih[c,v] + b_ih[c]  (exact fp32; one-hot dot is exact)
// ---------------------------------------------------------------------------
__global__ void build_gi_kernel(const float* __restrict__ Wih,
                                const float* __restrict__ bih)
{
    int idx = blockIdx.x * blockDim.x + threadIdx.x;
    if (idx >= V_ * 3 * H_) return;
    int v = idx / (3 * H_);
    int c = idx % (3 * H_);
    g_GI[idx] = __fadd_rn(Wih[(size_t)c * V_ + v], bih[c]);
}

// ---------------------------------------------------------------------------
// gh = h @ W_hh^T + b_hh, plain exact fp32 FMA.  M=8192, N=3072, K=1024.
// (UNCHANGED from the passing R11 kernel — numerics are load-bearing.)
// ---------------------------------------------------------------------------
#define BM 128
#define BN 128
#define BK 16

__global__ __launch_bounds__(256, 2)
void gru_gemm_kernel(const float* __restrict__ ctx,
                     const float* __restrict__ Whh,
                     const float* __restrict__ bhh,
                     int use_ctx)
{
    const float* __restrict__ A = use_ctx ? ctx : g_h;
    float* __restrict__ C = g_gh;
    const int K = H_;
    const int N = 3 * H_;

    const int m0 = blockIdx.y * BM;
    const int n0 = blockIdx.x * BN;

    __shared__ float As[BK][BM + 4];
    __shared__ float Bs[BK][BN + 4];

    const int tid = threadIdx.x;
    const int tx = tid & 15;   // n micro
    const int ty = tid >> 4;   // m micro

    const int lrow = tid >> 2;        // 0..63
    const int lc4  = (tid & 3) << 2;  // 0,4,8,12

    float acc[8][8];
#pragma unroll
    for (int i = 0; i < 8; ++i)
#pragma unroll
        for (int j = 0; j < 8; ++j) acc[i][j] = 0.0f;

    for (int kt = 0; kt < K; kt += BK) {
#pragma unroll
        for (int r = 0; r < 2; ++r) {
            int m = lrow + r * 64;
            float4 a = *(const float4*)(A   + (size_t)(m0 + m) * K + kt + lc4);
            As[lc4 + 0][m] = a.x; As[lc4 + 1][m] = a.y;
            As[lc4 + 2][m] = a.z; As[lc4 + 3][m] = a.w;
            float4 b = *(const float4*)(Whh + (size_t)(n0 + m) * K + kt + lc4);
            Bs[lc4 + 0][m] = b.x; Bs[lc4 + 1][m] = b.y;
            Bs[lc4 + 2][m] = b.z; Bs[lc4 + 3][m] = b.w;
        }
        __syncthreads();

#pragma unroll
        for (int k = 0; k < BK; ++k) {
            float ra[8], rb[8];
#pragma unroll
            for (int i = 0; i < 8; ++i) ra[i] = As[k][ty * 8 + i];
#pragma unroll
            for (int j = 0; j < 8; ++j) rb[j] = Bs[k][tx * 8 + j];
#pragma unroll
            for (int i = 0; i < 8; ++i)
#pragma unroll
                for (int j = 0; j < 8; ++j)
                    acc[i][j] = fmaf(ra[i], rb[j], acc[i][j]);
        }
        __syncthreads();
    }

#pragma unroll
    for (int i = 0; i < 8; ++i) {
        int m = m0 + ty * 8 + i;
#pragma unroll
        for (int j = 0; j < 8; j += 4) {
            int n = n0 + tx * 8 + j;
            float4 o;
            o.x = __fadd_rn(acc[i][j + 0], bhh[n + 0]);
            o.y = __fadd_rn(acc[i][j + 1], bhh[n + 1]);
            o.z = __fadd_rn(acc[i][j + 2], bhh[n + 2]);
            o.w = __fadd_rn(acc[i][j + 3], bhh[n + 3]);
            *(float4*)(C + (size_t)m * N + n) = o;
        }
    }
}

// ---------------------------------------------------------------------------
// Fused update, ROWS=8 batch rows per block. Numerics BIT-IDENTICAL to R11:
//  - gates: same pinned op sequence per element (elementwise, order-free)
//  - logits: per (v,row), lane l accumulates chunks i=0..7 at float4 index
//    (l + 32 i) with fmaf x,y,z,w then the same shfl_down tree, then +bout.
//    W_out row now loaded ONCE into registers and reused across 8 rows
//    (kills the 2 GB/step L2 streaming of the one-row-per-block version).
//  - softmax/argmax: same serial per-row algorithm (1 thread per row).
// ---------------------------------------------------------------------------
__global__ __launch_bounds__(256)
void gru_update_kernel(const float* __restrict__ ctx,
                       const float* __restrict__ Wout,
                       const float* __restrict__ bout,
                       float* __restrict__ logp_out,   // [B, T, V]
                       float* __restrict__ pred_out,   // [B, T] as float, or null
                       int t, int T, int use_ctx)
{
    const int r0  = blockIdx.x * ROWS;
    const int tid = threadIdx.x;
    const int warp = tid >> 5;
    const int lane = tid & 31;

    __shared__ float sh[ROWS][H_];      // 32 KB: new h for 8 rows
    __shared__ float slog[ROWS][V_];    // logits -> shifted logits
    __shared__ float s_lse[ROWS];
    __shared__ int   stok[ROWS];

    if (tid < ROWS) stok[tid] = use_ctx ? 0 : g_tok[r0 + tid];
    __syncthreads();

    // ---- gates (pinned math, identical per element) ----
    for (int e = tid; e < ROWS * H_; e += 256) {
        int rr = e >> 10;            // e / H_
        int j  = e & (H_ - 1);       // e % H_
        int b  = r0 + rr;
        const float* __restrict__ gi  = g_GI + (size_t)stok[rr] * 3 * H_;
        const float* __restrict__ ghb = g_gh + (size_t)b * 3 * H_;
        float hp = use_ctx ? ctx[(size_t)b * H_ + j] : g_h[(size_t)b * H_ + j];
        float r  = sigmoid_xla(__fadd_rn(gi[j],          ghb[j]));
        float z  = sigmoid_xla(__fadd_rn(gi[j + H_],     ghb[j + H_]));
        float rn = __fmul_rn(r, ghb[j + 2 * H_]);
        float n  = tanh_xla(__fadd_rn(gi[j + 2 * H_], rn));
        float a1 = __fmul_rn(__fsub_rn(1.0f, z), n);
        float a2 = __fmul_rn(z, hp);
        float hv = __fadd_rn(a1, a2);
        sh[rr][j] = hv;
        g_h[(size_t)b * H_ + j] = hv;
    }
    __syncthreads();

    // ---- logits: warp w covers v = w*8 .. w*8+7 ----
#pragma unroll
    for (int vi = 0; vi < 8; ++vi) {
        int v = warp * 8 + vi;
        const float4* __restrict__ w4 = (const float4*)(Wout + (size_t)v * H_);
        float4 wr[8];
#pragma unroll
        for (int i = 0; i < 8; ++i) wr[i] = w4[lane + i * 32];

#pragma unroll
        for (int rr = 0; rr < ROWS; ++rr) {
            const float4* __restrict__ h4 = (const float4*)sh[rr];
            float acc = 0.0f;
#pragma unroll
            for (int i = 0; i < 8; ++i) {
                float4 hh = h4[lane + i * 32];
                acc = fmaf(wr[i].x, hh.x, acc);
                acc = fmaf(wr[i].y, hh.y, acc);
                acc = fmaf(wr[i].z, hh.z, acc);
                acc = fmaf(wr[i].w, hh.w, acc);
            }
#pragma unroll
            for (int off = 16; off > 0; off >>= 1)
                acc += __shfl_down_sync(0xffffffffu, acc, off);
            if (lane == 0) slog[rr][v] = __fadd_rn(acc, bout[v]);
        }
    }
    __syncthreads();

    // ---- softmax + argmax: thread rr handles row rr (same serial algo) ----
    if (tid < ROWS) {
        int rr = tid;
        float mx = slog[rr][0];
        for (int v = 1; v < V_; ++v) mx = fmaxf(mx, slog[rr][v]);
        double s = 0.0;
        for (int v = 0; v < V_; ++v) {
            float sv = __fsub_rn(slog[rr][v], mx);
            slog[rr][v] = sv;                 // overwrite with shifted
            s += exp((double)sv);
        }
        float lse = (float)log(s);
        s_lse[rr] = lse;

        float best = __fsub_rn(slog[rr][0], lse);
        int am = 0;
        for (int v = 1; v < V_; ++v) {
            float lp = __fsub_rn(slog[rr][v], lse);
            if (lp > best) { best = lp; am = v; }   // first-index tie break
        }
        g_tok[r0 + rr] = am;
        if (pred_out) pred_out[(size_t)(r0 + rr) * T + t] = (float)am;
    }
    __syncthreads();

    // ---- write logp: 512 values, 2 per thread ----
    for (int e = tid; e < ROWS * V_; e += 256) {
        int rr = e >> 6;             // e / V_
        int v  = e & (V_ - 1);       // e % V_
        logp_out[((size_t)(r0 + rr) * T + t) * V_ + v] =
            __fsub_rn(slog[rr][v], s_lse[rr]);
    }
}

// ---------------------------------------------------------------------------
// Launch
// ---------------------------------------------------------------------------
extern "C" void kernel_launch(void* const* d_in, const int* in_sizes, int n_in,
                              void* d_out, int out_size)
{
    const float* ctx  = (const float*)d_in[0];  // [B, H]
    const float* Wih  = (const float*)d_in[1];  // [3H, V]
    const float* Whh  = (const float*)d_in[2];  // [3H, H]
    const float* bih  = (const float*)d_in[3];  // [3H]
    const float* bhh  = (const float*)d_in[4];  // [3H]
    const float* Wout = (const float*)d_in[5];  // [V, H]
    const float* bout = (const float*)d_in[6];  // [V]

    const int B = in_sizes[0] / H_;

    // Output layout: logps [B,T,V] possibly followed by preds [B,T] (float).
    float* out = (float*)d_out;
    float* logp_out = out;
    float* pred_out = nullptr;
    int T;
    const long per_both = (long)B * (V_ + 1);
    const long per_logp = (long)B * V_;
    if ((long)out_size % per_both == 0) {
        T = (int)((long)out_size / per_both);
        pred_out = out + (size_t)B * T * V_;
    } else {
        T = (int)((long)out_size / per_logp);
    }

    // Build GI table (exact fp32 W_ih column + bias)
    {
        int total = V_ * 3 * H_;
        build_gi_kernel<<<(total + 255) / 256, 256>>>(Wih, bih);
    }

    dim3 gemm_grid(3 * H_ / BN, B / BM);
    for (int t = 0; t < T; ++t) {
        int use_ctx = (t == 0) ? 1 : 0;
        gru_gemm_kernel<<<gemm_grid, 256>>>(ctx, Whh, bhh, use_ctx);
        gru_update_kernel<<<B / ROWS, 256>>>(ctx, Wout, bout, logp_out,
                                             pred_out, t, T, use_ctx);
    }
}

// round 15
// speedup vs baseline: 1.1478x; 1.0323x over previous
#include <cuda_runtime.h>
#include <cuda_bf16.h>
#include <math.h>
#include <stdint.h>

// GRUDecoder: B=8192, H=1024, V=64, T=15
#define B_MAX 8192
#define H_    1024
#define V_    64
#define N3    3072
#define ROWS  8

// Device-global scratch (no runtime allocation allowed)
__device__ float g_h[B_MAX * H_];          // hidden state (exact fp32)
__device__ float g_gh[B_MAX * N3];         // gh = fp32 gemm(h,Whh) + bhh
__device__ float g_GI[V_ * N3];            // GI[v][c] = W_ih[c,v] + b_ih[c]
__device__ int   g_tok[B_MAX];             // greedy feedback tokens

// ---------------------------------------------------------------------------
// Packed f32x2 helpers (Blackwell base-ISA; each lane is an IEEE-rn fp32 FMA,
// so results are BIT-IDENTICAL to the scalar fmaf chain they replace).
// ---------------------------------------------------------------------------
__device__ __forceinline__ void fma2(unsigned long long& acc,
                                     unsigned long long a,
                                     unsigned long long b) {
    asm("fma.rn.f32x2 %0, %1, %2, %0;" : "+l"(acc) : "l"(a), "l"(b));
}
__device__ __forceinline__ unsigned long long pack2(float lo, float hi) {
    unsigned long long r;
    asm("mov.b64 %0, {%1, %2};" : "=l"(r) : "f"(lo), "f"(hi));
    return r;
}
__device__ __forceinline__ void unpack2(float& lo, float& hi,
                                        unsigned long long v) {
    asm("mov.b64 {%0, %1}, %2;" : "=f"(lo), "=f"(hi) : "l"(v));
}

// XLA's f32 tanh (Eigen rational); fmaf + IEEE div => fast-math immune.
__device__ __forceinline__ float tanh_xla(float x) {
    const float kClamp = 7.90531110763549805f;
    float xc = fminf(fmaxf(x, -kClamp), kClamp);
    float x2 = __fmul_rn(xc, xc);
    float p = -2.76076847742355e-16f;
    p = fmaf(p, x2, 2.00018790482477e-13f);
    p = fmaf(p, x2, -8.60467152213735e-11f);
    p = fmaf(p, x2, 5.12229709037114e-08f);
    p = fmaf(p, x2, 1.48572235717979e-05f);
    p = fmaf(p, x2, 6.37261928875436e-04f);
    p = fmaf(p, x2, 4.89352455891786e-03f);
    p = __fmul_rn(p, xc);
    float q = 1.19825839466702e-06f;
    q = fmaf(q, x2, 1.18534705686654e-04f);
    q = fmaf(q, x2, 2.26843463243900e-03f);
    q = fmaf(q, x2, 4.89352518554385e-03f);
    float r = __fdiv_rn(p, q);
    return (fabsf(x) < 0.0004f) ? x : r;
}
__device__ __forceinline__ float sigmoid_xla(float x) {
    float t = tanh_xla(__fmul_rn(0.5f, x));
    return __fadd_rn(0.5f, __fmul_rn(0.5f, t));
}

// ---------------------------------------------------------------------------
// GI[v][c] = W_ih[c,v] + b_ih[c]
// ---------------------------------------------------------------------------
__global__ void build_gi_kernel(const float* __restrict__ Wih,
                                const float* __restrict__ bih)
{
    int idx = blockIdx.x * blockDim.x + threadIdx.x;
    if (idx >= V_ * N3) return;
    int v = idx / N3;
    int c = idx % N3;
    g_GI[idx] = __fadd_rn(Wih[(size_t)c * V_ + v], bih[c]);
}

// ---------------------------------------------------------------------------
// gh = h @ W_hh^T + b_hh, exact fp32, FFMA2 (f32x2) inner product.
// Per-element accumulation chain (k ascending, same op order) is identical
// to the passing R12 kernel => bit-identical g_gh.
// Double-buffered SMEM with register prefetch: 1 __syncthreads per K-tile.
// ---------------------------------------------------------------------------
#define BM 128
#define BN 128
#define BK 16
#define NIT (H_ / BK)   // 64

__global__ __launch_bounds__(256, 2)
void gru_gemm_kernel(const float* __restrict__ ctx,
                     const float* __restrict__ Whh,
                     const float* __restrict__ bhh,
                     int use_ctx)
{
    const float* __restrict__ A = use_ctx ? ctx : g_h;
    float* __restrict__ C = g_gh;
    const int K = H_;
    const int N = N3;

    const int m0 = blockIdx.y * BM;
    const int n0 = blockIdx.x * BN;

    __shared__ float As[2][BK][BM + 4];
    __shared__ float Bs[2][BK][BN + 4];

    const int tid = threadIdx.x;
    const int tx = tid & 15;   // n micro
    const int ty = tid >> 4;   // m micro

    const int lrow = tid >> 2;        // 0..63
    const int lc4  = (tid & 3) << 2;  // 0,4,8,12

    // accumulators: 8 m-rows x 4 n-pairs (each pair = 2 adjacent n columns)
    unsigned long long acc2[8][4];
#pragma unroll
    for (int i = 0; i < 8; ++i)
#pragma unroll
        for (int j = 0; j < 4; ++j) acc2[i][j] = 0ull;

    float4 pa[2], pb[2];

    // prologue: tile 0 -> regs -> smem[0]
#pragma unroll
    for (int r = 0; r < 2; ++r) {
        int m = lrow + r * 64;
        pa[r] = *(const float4*)(A   + (size_t)(m0 + m) * K + lc4);
        pb[r] = *(const float4*)(Whh + (size_t)(n0 + m) * K + lc4);
    }
#pragma unroll
    for (int r = 0; r < 2; ++r) {
        int m = lrow + r * 64;
        As[0][lc4 + 0][m] = pa[r].x; As[0][lc4 + 1][m] = pa[r].y;
        As[0][lc4 + 2][m] = pa[r].z; As[0][lc4 + 3][m] = pa[r].w;
        Bs[0][lc4 + 0][m] = pb[r].x; Bs[0][lc4 + 1][m] = pb[r].y;
        Bs[0][lc4 + 2][m] = pb[r].z; Bs[0][lc4 + 3][m] = pb[r].w;
    }
    __syncthreads();

    // issue loads for tile 1
#pragma unroll
    for (int r = 0; r < 2; ++r) {
        int m = lrow + r * 64;
        pa[r] = *(const float4*)(A   + (size_t)(m0 + m) * K + BK + lc4);
        pb[r] = *(const float4*)(Whh + (size_t)(n0 + m) * K + BK + lc4);
    }

    for (int it = 0; it < NIT; ++it) {
        const int cur = it & 1;

#pragma unroll
        for (int k = 0; k < BK; ++k) {
            float ra[8], rb[8];
#pragma unroll
            for (int i = 0; i < 8; ++i) ra[i] = As[cur][k][ty * 8 + i];
#pragma unroll
            for (int j = 0; j < 8; ++j) rb[j] = Bs[cur][k][tx * 8 + j];
            unsigned long long rbp[4];
#pragma unroll
            for (int j2 = 0; j2 < 4; ++j2)
                rbp[j2] = pack2(rb[2 * j2], rb[2 * j2 + 1]);
#pragma unroll
            for (int i = 0; i < 8; ++i) {
                unsigned long long rap = pack2(ra[i], ra[i]);
#pragma unroll
                for (int j2 = 0; j2 < 4; ++j2)
                    fma2(acc2[i][j2], rap, rbp[j2]);
            }
        }

        if (it + 1 < NIT) {
            const int nxt = cur ^ 1;
            // store prefetched tile (safe: buffer nxt's last readers were
            // compute(it-1), all warps passed the previous __syncthreads)
#pragma unroll
            for (int r = 0; r < 2; ++r) {
                int m = lrow + r * 64;
                As[nxt][lc4 + 0][m] = pa[r].x; As[nxt][lc4 + 1][m] = pa[r].y;
                As[nxt][lc4 + 2][m] = pa[r].z; As[nxt][lc4 + 3][m] = pa[r].w;
                Bs[nxt][lc4 + 0][m] = pb[r].x; Bs[nxt][lc4 + 1][m] = pb[r].y;
                Bs[nxt][lc4 + 2][m] = pb[r].z; Bs[nxt][lc4 + 3][m] = pb[r].w;
            }
            __syncthreads();
            if (it + 2 < NIT) {
                int kt = (it + 2) * BK;
#pragma unroll
                for (int r = 0; r < 2; ++r) {
                    int m = lrow + r * 64;
                    pa[r] = *(const float4*)(A   + (size_t)(m0 + m) * K + kt + lc4);
                    pb[r] = *(const float4*)(Whh + (size_t)(n0 + m) * K + kt + lc4);
                }
            }
        }
    }

#pragma unroll
    for (int i = 0; i < 8; ++i) {
        int m = m0 + ty * 8 + i;
#pragma unroll
        for (int j2 = 0; j2 < 4; j2 += 2) {
            int n = n0 + tx * 8 + j2 * 2;
            float a0, a1, a2, a3;
            unpack2(a0, a1, acc2[i][j2]);
            unpack2(a2, a3, acc2[i][j2 + 1]);
            float4 o;
            o.x = __fadd_rn(a0, bhh[n + 0]);
            o.y = __fadd_rn(a1, bhh[n + 1]);
            o.z = __fadd_rn(a2, bhh[n + 2]);
            o.w = __fadd_rn(a3, bhh[n + 3]);
            *(float4*)(C + (size_t)m * N + n) = o;
        }
    }
}

// ---------------------------------------------------------------------------
// Fused update (UNCHANGED from passing R12 — numerics are load-bearing).
// ---------------------------------------------------------------------------
__global__ __launch_bounds__(256)
void gru_update_kernel(const float* __restrict__ ctx,
                       const float* __restrict__ Wout,
                       const float* __restrict__ bout,
                       float* __restrict__ logp_out,
                       float* __restrict__ pred_out,
                       int t, int T, int use_ctx)
{
    const int r0  = blockIdx.x * ROWS;
    const int tid = threadIdx.x;
    const int warp = tid >> 5;
    const int lane = tid & 31;

    __shared__ float sh[ROWS][H_];
    __shared__ float slog[ROWS][V_];
    __shared__ float s_lse[ROWS];
    __shared__ int   stok[ROWS];

    if (tid < ROWS) stok[tid] = use_ctx ? 0 : g_tok[r0 + tid];
    __syncthreads();

    for (int e = tid; e < ROWS * H_; e += 256) {
        int rr = e >> 10;
        int j  = e & (H_ - 1);
        int b  = r0 + rr;
        const float* __restrict__ gi  = g_GI + (size_t)stok[rr] * N3;
        const float* __restrict__ ghb = g_gh + (size_t)b * N3;
        float hp = use_ctx ? ctx[(size_t)b * H_ + j] : g_h[(size_t)b * H_ + j];
        float r  = sigmoid_xla(__fadd_rn(gi[j],          ghb[j]));
        float z  = sigmoid_xla(__fadd_rn(gi[j + H_],     ghb[j + H_]));
        float rn = __fmul_rn(r, ghb[j + 2 * H_]);
        float n  = tanh_xla(__fadd_rn(gi[j + 2 * H_], rn));
        float a1 = __fmul_rn(__fsub_rn(1.0f, z), n);
        float a2 = __fmul_rn(z, hp);
        float hv = __fadd_rn(a1, a2);
        sh[rr][j] = hv;
        g_h[(size_t)b * H_ + j] = hv;
    }
    __syncthreads();

#pragma unroll
    for (int vi = 0; vi < 8; ++vi) {
        int v = warp * 8 + vi;
        const float4* __restrict__ w4 = (const float4*)(Wout + (size_t)v * H_);
        float4 wr[8];
#pragma unroll
        for (int i = 0; i < 8; ++i) wr[i] = w4[lane + i * 32];
#pragma unroll
        for (int rr = 0; rr < ROWS; ++rr) {
            const float4* __restrict__ h4 = (const float4*)sh[rr];
            float acc = 0.0f;
#pragma unroll
            for (int i = 0; i < 8; ++i) {
                float4 hh = h4[lane + i * 32];
                acc = fmaf(wr[i].x, hh.x, acc);
                acc = fmaf(wr[i].y, hh.y, acc);
                acc = fmaf(wr[i].z, hh.z, acc);
                acc = fmaf(wr[i].w, hh.w, acc);
            }
#pragma unroll
            for (int off = 16; off > 0; off >>= 1)
                acc += __shfl_down_sync(0xffffffffu, acc, off);
            if (lane == 0) slog[rr][v] = __fadd_rn(acc, bout[v]);
        }
    }
    __syncthreads();

    if (tid < ROWS) {
        int rr = tid;
        float mx = slog[rr][0];
        for (int v = 1; v < V_; ++v) mx = fmaxf(mx, slog[rr][v]);
        double s = 0.0;
        for (int v = 0; v < V_; ++v) {
            float sv = __fsub_rn(slog[rr][v], mx);
            slog[rr][v] = sv;
            s += exp((double)sv);
        }
        float lse = (float)log(s);
        s_lse[rr] = lse;
        float best = __fsub_rn(slog[rr][0], lse);
        int am = 0;
        for (int v = 1; v < V_; ++v) {
            float lp = __fsub_rn(slog[rr][v], lse);
            if (lp > best) { best = lp; am = v; }
        }
        g_tok[r0 + rr] = am;
        if (pred_out) pred_out[(size_t)(r0 + rr) * T + t] = (float)am;
    }
    __syncthreads();

    for (int e = tid; e < ROWS * V_; e += 256) {
        int rr = e >> 6;
        int v  = e & (V_ - 1);
        logp_out[((size_t)(r0 + rr) * T + t) * V_ + v] =
            __fsub_rn(slog[rr][v], s_lse[rr]);
    }
}

// ---------------------------------------------------------------------------
// Launch
// ---------------------------------------------------------------------------
extern "C" void kernel_launch(void* const* d_in, const int* in_sizes, int n_in,
                              void* d_out, int out_size)
{
    const float* ctx  = (const float*)d_in[0];
    const float* Wih  = (const float*)d_in[1];
    const float* Whh  = (const float*)d_in[2];
    const float* bih  = (const float*)d_in[3];
    const float* bhh  = (const float*)d_in[4];
    const float* Wout = (const float*)d_in[5];
    const float* bout = (const float*)d_in[6];

    const int B = in_sizes[0] / H_;

    float* out = (float*)d_out;
    float* logp_out = out;
    float* pred_out = nullptr;
    int T;
    const long per_both = (long)B * (V_ + 1);
    const long per_logp = (long)B * V_;
    if ((long)out_size % per_both == 0) {
        T = (int)((long)out_size / per_both);
        pred_out = out + (size_t)B * T * V_;
    } else {
        T = (int)((long)out_size / per_logp);
    }

    build_gi_kernel<<<(V_ * N3 + 255) / 256, 256>>>(Wih, bih);

    dim3 gemm_grid(N3 / BN, B / BM);
    for (int t = 0; t < T; ++t) {
        int use_ctx = (t == 0) ? 1 : 0;
        gru_gemm_kernel<<<gemm_grid, 256>>>(ctx, Whh, bhh, use_ctx);
        gru_update_kernel<<<B / ROWS, 256>>>(ctx, Wout, bout, logp_out,
                                             pred_out, t, T, use_ctx);
    }
}

// round 16
// speedup vs baseline: 1.3209x; 1.1508x over previous
#include <cuda_runtime.h>
#include <cuda_bf16.h>
#include <math.h>
#include <stdint.h>

// GRUDecoder: B=8192, H=1024, V=64, T=15
#define B_MAX 8192
#define H_    1024
#define V_    64
#define N3    3072
#define ROWS  8

// Device-global scratch (no runtime allocation allowed)
__device__ float g_h[B_MAX * H_];          // hidden state (exact fp32)
__device__ float g_gh[B_MAX * N3];         // gh = fp32 gemm(h,Whh) + bhh
__device__ float g_GI[V_ * N3];            // GI[v][c] = W_ih[c,v] + b_ih[c]
__device__ int   g_tok[B_MAX];             // greedy feedback tokens

// ---------------------------------------------------------------------------
// Packed f32x2 helpers. Each lane is an independent IEEE-rn fp32 op, so
// per-element results are BIT-IDENTICAL to the scalar chains they replace.
// ---------------------------------------------------------------------------
typedef unsigned long long u64t;
__device__ __forceinline__ u64t pack2(float lo, float hi) {
    u64t r; asm("mov.b64 %0, {%1, %2};" : "=l"(r) : "f"(lo), "f"(hi)); return r;
}
__device__ __forceinline__ void unpack2(float& lo, float& hi, u64t v) {
    asm("mov.b64 {%0, %1}, %2;" : "=f"(lo), "=f"(hi) : "l"(v));
}
__device__ __forceinline__ void fma2acc(u64t& acc, u64t a, u64t b) {
    asm("fma.rn.f32x2 %0, %1, %2, %0;" : "+l"(acc) : "l"(a), "l"(b));
}
__device__ __forceinline__ u64t fma2(u64t a, u64t b, u64t c) {
    u64t d; asm("fma.rn.f32x2 %0, %1, %2, %3;" : "=l"(d) : "l"(a), "l"(b), "l"(c));
    return d;
}
__device__ __forceinline__ u64t mul2(u64t a, u64t b) {
    u64t d; asm("mul.rn.f32x2 %0, %1, %2;" : "=l"(d) : "l"(a), "l"(b)); return d;
}
__device__ __forceinline__ u64t add2(u64t a, u64t b) {
    u64t d; asm("add.rn.f32x2 %0, %1, %2;" : "=l"(d) : "l"(a), "l"(b)); return d;
}

// XLA's f32 tanh (Eigen rational); scalar version (fast-math immune).
__device__ __forceinline__ float tanh_xla(float x) {
    const float kClamp = 7.90531110763549805f;
    float xc = fminf(fmaxf(x, -kClamp), kClamp);
    float x2 = __fmul_rn(xc, xc);
    float p = -2.76076847742355e-16f;
    p = fmaf(p, x2, 2.00018790482477e-13f);
    p = fmaf(p, x2, -8.60467152213735e-11f);
    p = fmaf(p, x2, 5.12229709037114e-08f);
    p = fmaf(p, x2, 1.48572235717979e-05f);
    p = fmaf(p, x2, 6.37261928875436e-04f);
    p = fmaf(p, x2, 4.89352455891786e-03f);
    p = __fmul_rn(p, xc);
    float q = 1.19825839466702e-06f;
    q = fmaf(q, x2, 1.18534705686654e-04f);
    q = fmaf(q, x2, 2.26843463243900e-03f);
    q = fmaf(q, x2, 4.89352518554385e-03f);
    float r = __fdiv_rn(p, q);
    return (fabsf(x) < 0.0004f) ? x : r;
}
__device__ __forceinline__ float sigmoid_xla(float x) {
    float t = tanh_xla(__fmul_rn(0.5f, x));
    return __fadd_rn(0.5f, __fmul_rn(0.5f, t));
}

// Packed 2-lane tanh: identical op sequence per lane (clamp scalar, poly in
// f32x2, IEEE div + select scalar). Bit-identical to tanh_xla per element.
__device__ __forceinline__ void tanh2_xla(float xlo, float xhi,
                                          float& rlo, float& rhi) {
    const float kClamp = 7.90531110763549805f;
    float clo = fminf(fmaxf(xlo, -kClamp), kClamp);
    float chi = fminf(fmaxf(xhi, -kClamp), kClamp);
    u64t xc = pack2(clo, chi);
    u64t x2 = mul2(xc, xc);
    u64t p = pack2(-2.76076847742355e-16f, -2.76076847742355e-16f);
    p = fma2(p, x2, pack2(2.00018790482477e-13f, 2.00018790482477e-13f));
    p = fma2(p, x2, pack2(-8.60467152213735e-11f, -8.60467152213735e-11f));
    p = fma2(p, x2, pack2(5.12229709037114e-08f, 5.12229709037114e-08f));
    p = fma2(p, x2, pack2(1.48572235717979e-05f, 1.48572235717979e-05f));
    p = fma2(p, x2, pack2(6.37261928875436e-04f, 6.37261928875436e-04f));
    p = fma2(p, x2, pack2(4.89352455891786e-03f, 4.89352455891786e-03f));
    p = mul2(p, xc);
    u64t q = pack2(1.19825839466702e-06f, 1.19825839466702e-06f);
    q = fma2(q, x2, pack2(1.18534705686654e-04f, 1.18534705686654e-04f));
    q = fma2(q, x2, pack2(2.26843463243900e-03f, 2.26843463243900e-03f));
    q = fma2(q, x2, pack2(4.89352518554385e-03f, 4.89352518554385e-03f));
    float plo, phi, qlo, qhi;
    unpack2(plo, phi, p);
    unpack2(qlo, qhi, q);
    float dlo = __fdiv_rn(plo, qlo);
    float dhi = __fdiv_rn(phi, qhi);
    rlo = (fabsf(xlo) < 0.0004f) ? xlo : dlo;
    rhi = (fabsf(xhi) < 0.0004f) ? xhi : dhi;
}
// Packed sigmoid: per lane == __fadd_rn(0.5, __fmul_rn(0.5, tanh(0.5*x)))
__device__ __forceinline__ void sigmoid2_xla(float xlo, float xhi,
                                             float& rlo, float& rhi) {
    float tlo, thi;
    tanh2_xla(__fmul_rn(0.5f, xlo), __fmul_rn(0.5f, xhi), tlo, thi);
    rlo = __fadd_rn(0.5f, __fmul_rn(0.5f, tlo));
    rhi = __fadd_rn(0.5f, __fmul_rn(0.5f, thi));
}

// ---------------------------------------------------------------------------
// GI[v][c] = W_ih[c,v] + b_ih[c]
// ---------------------------------------------------------------------------
__global__ void build_gi_kernel(const float* __restrict__ Wih,
                                const float* __restrict__ bih)
{
    int idx = blockIdx.x * blockDim.x + threadIdx.x;
    if (idx >= V_ * N3) return;
    int v = idx / N3;
    int c = idx % N3;
    g_GI[idx] = __fadd_rn(Wih[(size_t)c * V_ + v], bih[c]);
}

// ---------------------------------------------------------------------------
// gh = h @ W_hh^T + b_hh, exact fp32, FFMA2 inner product, LDS.128 fragment
// reads (same values/order as R15 => bit-identical). Double-buffered SMEM.
// ---------------------------------------------------------------------------
#define BM 128
#define BN 128
#define BK 16
#define NIT (H_ / BK)   // 64

__global__ __launch_bounds__(256, 2)
void gru_gemm_kernel(const float* __restrict__ ctx,
                     const float* __restrict__ Whh,
                     const float* __restrict__ bhh,
                     int use_ctx)
{
    const float* __restrict__ A = use_ctx ? ctx : g_h;
    float* __restrict__ C = g_gh;
    const int K = H_;
    const int N = N3;

    const int m0 = blockIdx.y * BM;
    const int n0 = blockIdx.x * BN;

    __shared__ float As[2][BK][BM + 4];
    __shared__ float Bs[2][BK][BN + 4];

    const int tid = threadIdx.x;
    const int tx = tid & 15;   // n micro
    const int ty = tid >> 4;   // m micro

    const int lrow = tid >> 2;        // 0..63
    const int lc4  = (tid & 3) << 2;  // 0,4,8,12

    unsigned long long acc2[8][4];
#pragma unroll
    for (int i = 0; i < 8; ++i)
#pragma unroll
        for (int j = 0; j < 4; ++j) acc2[i][j] = 0ull;

    float4 pa[2], pb[2];

#pragma unroll
    for (int r = 0; r < 2; ++r) {
        int m = lrow + r * 64;
        pa[r] = *(const float4*)(A   + (size_t)(m0 + m) * K + lc4);
        pb[r] = *(const float4*)(Whh + (size_t)(n0 + m) * K + lc4);
    }
#pragma unroll
    for (int r = 0; r < 2; ++r) {
        int m = lrow + r * 64;
        As[0][lc4 + 0][m] = pa[r].x; As[0][lc4 + 1][m] = pa[r].y;
        As[0][lc4 + 2][m] = pa[r].z; As[0][lc4 + 3][m] = pa[r].w;
        Bs[0][lc4 + 0][m] = pb[r].x; Bs[0][lc4 + 1][m] = pb[r].y;
        Bs[0][lc4 + 2][m] = pb[r].z; Bs[0][lc4 + 3][m] = pb[r].w;
    }
    __syncthreads();

#pragma unroll
    for (int r = 0; r < 2; ++r) {
        int m = lrow + r * 64;
        pa[r] = *(const float4*)(A   + (size_t)(m0 + m) * K + BK + lc4);
        pb[r] = *(const float4*)(Whh + (size_t)(n0 + m) * K + BK + lc4);
    }

    for (int it = 0; it < NIT; ++it) {
        const int cur = it & 1;

#pragma unroll
        for (int k = 0; k < BK; ++k) {
            // LDS.128 fragment reads (16B-aligned: row stride 132 floats,
            // offsets 32B-aligned) — same values as 16 scalar LDS.32.
            const float4* pAv = (const float4*)&As[cur][k][ty * 8];
            const float4* pBv = (const float4*)&Bs[cur][k][tx * 8];
            float4 ra0 = pAv[0], ra1 = pAv[1];
            float4 rb0 = pBv[0], rb1 = pBv[1];

            unsigned long long rbp[4];
            rbp[0] = pack2(rb0.x, rb0.y);
            rbp[1] = pack2(rb0.z, rb0.w);
            rbp[2] = pack2(rb1.x, rb1.y);
            rbp[3] = pack2(rb1.z, rb1.w);
            float ra[8] = {ra0.x, ra0.y, ra0.z, ra0.w,
                           ra1.x, ra1.y, ra1.z, ra1.w};
#pragma unroll
            for (int i = 0; i < 8; ++i) {
                unsigned long long rap = pack2(ra[i], ra[i]);
#pragma unroll
                for (int j2 = 0; j2 < 4; ++j2)
                    fma2acc(acc2[i][j2], rap, rbp[j2]);
            }
        }

        if (it + 1 < NIT) {
            const int nxt = cur ^ 1;
#pragma unroll
            for (int r = 0; r < 2; ++r) {
                int m = lrow + r * 64;
                As[nxt][lc4 + 0][m] = pa[r].x; As[nxt][lc4 + 1][m] = pa[r].y;
                As[nxt][lc4 + 2][m] = pa[r].z; As[nxt][lc4 + 3][m] = pa[r].w;
                Bs[nxt][lc4 + 0][m] = pb[r].x; Bs[nxt][lc4 + 1][m] = pb[r].y;
                Bs[nxt][lc4 + 2][m] = pb[r].z; Bs[nxt][lc4 + 3][m] = pb[r].w;
            }
            __syncthreads();
            if (it + 2 < NIT) {
                int kt = (it + 2) * BK;
#pragma unroll
                for (int r = 0; r < 2; ++r) {
                    int m = lrow + r * 64;
                    pa[r] = *(const float4*)(A   + (size_t)(m0 + m) * K + kt + lc4);
                    pb[r] = *(const float4*)(Whh + (size_t)(n0 + m) * K + kt + lc4);
                }
            }
        }
    }

#pragma unroll
    for (int i = 0; i < 8; ++i) {
        int m = m0 + ty * 8 + i;
#pragma unroll
        for (int j2 = 0; j2 < 4; j2 += 2) {
            int n = n0 + tx * 8 + j2 * 2;
            float a0, a1, a2, a3;
            unpack2(a0, a1, acc2[i][j2]);
            unpack2(a2, a3, acc2[i][j2 + 1]);
            float4 o;
            o.x = __fadd_rn(a0, bhh[n + 0]);
            o.y = __fadd_rn(a1, bhh[n + 1]);
            o.z = __fadd_rn(a2, bhh[n + 2]);
            o.w = __fadd_rn(a3, bhh[n + 3]);
            *(float4*)(C + (size_t)m * N + n) = o;
        }
    }
}

// ---------------------------------------------------------------------------
// Fused update: gates now processed 2 elements/thread with packed-f32x2
// polynomials (per-element numerics bit-identical to R12). Logits/softmax/
// argmax unchanged.
// ---------------------------------------------------------------------------
__global__ __launch_bounds__(256)
void gru_update_kernel(const float* __restrict__ ctx,
                       const float* __restrict__ Wout,
                       const float* __restrict__ bout,
                       float* __restrict__ logp_out,
                       float* __restrict__ pred_out,
                       int t, int T, int use_ctx)
{
    const int r0  = blockIdx.x * ROWS;
    const int tid = threadIdx.x;
    const int warp = tid >> 5;
    const int lane = tid & 31;

    __shared__ float sh[ROWS][H_];
    __shared__ float slog[ROWS][V_];
    __shared__ float s_lse[ROWS];
    __shared__ int   stok[ROWS];

    if (tid < ROWS) stok[tid] = use_ctx ? 0 : g_tok[r0 + tid];
    __syncthreads();

    // gates: 2 consecutive j per thread iteration (ROWS*H_/2 = 4096 pairs)
    for (int e2 = tid; e2 < ROWS * (H_ / 2); e2 += 256) {
        int rr = e2 >> 9;                 // e2 / (H_/2)
        int j  = (e2 & ((H_ / 2) - 1)) * 2;
        int b  = r0 + rr;
        const float* __restrict__ gi  = g_GI + (size_t)stok[rr] * N3;
        const float* __restrict__ ghb = g_gh + (size_t)b * N3;
        const float* __restrict__ hin = (use_ctx ? ctx : g_h) + (size_t)b * H_;

        float2 gi0  = *(const float2*)(gi  + j);
        float2 gh0  = *(const float2*)(ghb + j);
        float2 gi1  = *(const float2*)(gi  + j + H_);
        float2 gh1  = *(const float2*)(ghb + j + H_);
        float2 gi2  = *(const float2*)(gi  + j + 2 * H_);
        float2 gh2  = *(const float2*)(ghb + j + 2 * H_);
        float2 hp2  = *(const float2*)(hin + j);

        // x_r = gi0 + gh0 ; x_z = gi1 + gh1   (packed add, rn per lane)
        float xr_lo, xr_hi, xz_lo, xz_hi;
        unpack2(xr_lo, xr_hi, add2(pack2(gi0.x, gi0.y), pack2(gh0.x, gh0.y)));
        unpack2(xz_lo, xz_hi, add2(pack2(gi1.x, gi1.y), pack2(gh1.x, gh1.y)));

        float r_lo, r_hi, z_lo, z_hi;
        sigmoid2_xla(xr_lo, xr_hi, r_lo, r_hi);
        sigmoid2_xla(xz_lo, xz_hi, z_lo, z_hi);

        // rn = r * gh2 ; xn = gi2 + rn  (packed mul/add, rn per lane)
        float xn_lo, xn_hi;
        unpack2(xn_lo, xn_hi,
                add2(pack2(gi2.x, gi2.y),
                     mul2(pack2(r_lo, r_hi), pack2(gh2.x, gh2.y))));

        float n_lo, n_hi;
        tanh2_xla(xn_lo, xn_hi, n_lo, n_hi);

        // hv = (1-z)*n + z*hp  (scalar pinned chain, identical to R12)
        float hv_lo, hv_hi;
        {
            float a1 = __fmul_rn(__fsub_rn(1.0f, z_lo), n_lo);
            float a2 = __fmul_rn(z_lo, hp2.x);
            hv_lo = __fadd_rn(a1, a2);
        }
        {
            float a1 = __fmul_rn(__fsub_rn(1.0f, z_hi), n_hi);
            float a2 = __fmul_rn(z_hi, hp2.y);
            hv_hi = __fadd_rn(a1, a2);
        }

        float2 hv2 = make_float2(hv_lo, hv_hi);
        *(float2*)&sh[rr][j] = hv2;
        *(float2*)(g_h + (size_t)b * H_ + j) = hv2;
    }
    __syncthreads();

    // logits (UNCHANGED numerics)
#pragma unroll
    for (int vi = 0; vi < 8; ++vi) {
        int v = warp * 8 + vi;
        const float4* __restrict__ w4 = (const float4*)(Wout + (size_t)v * H_);
        float4 wr[8];
#pragma unroll
        for (int i = 0; i < 8; ++i) wr[i] = w4[lane + i * 32];
#pragma unroll
        for (int rr = 0; rr < ROWS; ++rr) {
            const float4* __restrict__ h4 = (const float4*)sh[rr];
            float acc = 0.0f;
#pragma unroll
            for (int i = 0; i < 8; ++i) {
                float4 hh = h4[lane + i * 32];
                acc = fmaf(wr[i].x, hh.x, acc);
                acc = fmaf(wr[i].y, hh.y, acc);
                acc = fmaf(wr[i].z, hh.z, acc);
                acc = fmaf(wr[i].w, hh.w, acc);
            }
#pragma unroll
            for (int off = 16; off > 0; off >>= 1)
                acc += __shfl_down_sync(0xffffffffu, acc, off);
            if (lane == 0) slog[rr][v] = __fadd_rn(acc, bout[v]);
        }
    }
    __syncthreads();

    if (tid < ROWS) {
        int rr = tid;
        float mx = slog[rr][0];
        for (int v = 1; v < V_; ++v) mx = fmaxf(mx, slog[rr][v]);
        double s = 0.0;
        for (int v = 0; v < V_; ++v) {
            float sv = __fsub_rn(slog[rr][v], mx);
            slog[rr][v] = sv;
            s += exp((double)sv);
        }
        float lse = (float)log(s);
        s_lse[rr] = lse;
        float best = __fsub_rn(slog[rr][0], lse);
        int am = 0;
        for (int v = 1; v < V_; ++v) {
            float lp = __fsub_rn(slog[rr][v], lse);
            if (lp > best) { best = lp; am = v; }
        }
        g_tok[r0 + rr] = am;
        if (pred_out) pred_out[(size_t)(r0 + rr) * T + t] = (float)am;
    }
    __syncthreads();

    for (int e = tid; e < ROWS * V_; e += 256) {
        int rr = e >> 6;
        int v  = e & (V_ - 1);
        logp_out[((size_t)(r0 + rr) * T + t) * V_ + v] =
            __fsub_rn(slog[rr][v], s_lse[rr]);
    }
}

// ---------------------------------------------------------------------------
// Launch
// ---------------------------------------------------------------------------
extern "C" void kernel_launch(void* const* d_in, const int* in_sizes, int n_in,
                              void* d_out, int out_size)
{
    const float* ctx  = (const float*)d_in[0];
    const float* Wih  = (const float*)d_in[1];
    const float* Whh  = (const float*)d_in[2];
    const float* bih  = (const float*)d_in[3];
    const float* bhh  = (const float*)d_in[4];
    const float* Wout = (const float*)d_in[5];
    const float* bout = (const float*)d_in[6];

    const int B = in_sizes[0] / H_;

    float* out = (float*)d_out;
    float* logp_out = out;
    float* pred_out = nullptr;
    int T;
    const long per_both = (long)B * (V_ + 1);
    const long per_logp = (long)B * V_;
    if ((long)out_size % per_both == 0) {
        T = (int)((long)out_size / per_both);
        pred_out = out + (size_t)B * T * V_;
    } else {
        T = (int)((long)out_size / per_logp);
    }

    build_gi_kernel<<<(V_ * N3 + 255) / 256, 256>>>(Wih, bih);

    dim3 gemm_grid(N3 / BN, B / BM);
    for (int t = 0; t < T; ++t) {
        int use_ctx = (t == 0) ? 1 : 0;
        gru_gemm_kernel<<<gemm_grid, 256>>>(ctx, Whh, bhh, use_ctx);
        gru_update_kernel<<<B / ROWS, 256>>>(ctx, Wout, bout, logp_out,
                                             pred_out, t, T, use_ctx);
    }
}